// round 1
// baseline (speedup 1.0000x reference)
#include <cuda_runtime.h>
#include <math.h>

// ---------------- problem constants ----------------
#define BB 4
#define LL 2048
#define DD 128
#define MM (BB*LL)          // 8192 rows
#define PER_B (DD*LL)       // 262144 elements per batch per [D][L] buffer
#define TOT (BB*PER_B)      // 1048576

typedef unsigned long long u64;

// ---------------- scratch (static device memory; no allocation) ----------------
__device__ float g_pk[TOT];     // projection outputs [b][l][d] == conv input [b][c][s]
__device__ float g_pq[TOT];
__device__ float g_pv[TOT];
__device__ float g_ck[TOT];     // conv+silu outputs [b][c][s]
__device__ float g_cq[TOT];
__device__ float g_cv[TOT];
__device__ float g_kT[TOT];     // normalized, transposed [b][t][c]
__device__ float g_qT[TOT];
__device__ float g_vT[TOT];
__device__ float g_dT[TOT];     // delta output [b][t][c]
__device__ float g_normed[TOT]; // rms-normalized delta
__device__ float g_beta[MM];
__device__ float g_ninv[2*512]; // inv l2 norms for k (0..511) and q (512..1023)

// ---------------- f32x2 helpers (sm_10x packed fp32 FMA) ----------------
__device__ __forceinline__ u64 pk2(float x, float y) {
    u64 r; asm("mov.b64 %0, {%1, %2};" : "=l"(r) : "f"(x), "f"(y)); return r;
}
__device__ __forceinline__ u64 fma2(u64 a, u64 b, u64 c) {
    u64 d; asm("fma.rn.f32x2 %0, %1, %2, %3;" : "=l"(d) : "l"(a), "l"(b), "l"(c)); return d;
}
__device__ __forceinline__ void upk2(u64 v, float& x, float& y) {
    asm("mov.b64 {%0, %1}, %2;" : "=f"(x), "=f"(y) : "l"(v));
}
__device__ __forceinline__ float wsum(float v) {
    #pragma unroll
    for (int o = 16; o > 0; o >>= 1) v += __shfl_xor_sync(0xffffffffu, v, o);
    return v;
}

// =====================================================================
// Kernel 1: fused k/q/v projection GEMM.
// C[8192,384] = X[8192,2048] @ Wcat^T, tiles BM=128 BN=64 BK=16, 128 thr,
// thread tile 8x8, accumulators packed f32x2 (pairs along n).
// n-tile -> which projection: sel = nt>>1, d0 = (nt&1)*64.
// =====================================================================
__global__ void __launch_bounds__(128) gemm_proj(
    const float* __restrict__ X,
    const float* __restrict__ Wk, const float* __restrict__ Wq, const float* __restrict__ Wv,
    const float* __restrict__ bk, const float* __restrict__ bq, const float* __restrict__ bv)
{
    __shared__ float As[16][128];
    __shared__ float Bs[16][64];
    const int t   = threadIdx.x;
    const int nt  = blockIdx.x;           // 0..5
    const int m0  = blockIdx.y * 128;
    const int sel = nt >> 1;
    const int d0  = (nt & 1) * 64;
    const float* W    = (sel == 0) ? Wk : (sel == 1) ? Wq : Wv;
    const float* bias = (sel == 0) ? bk : (sel == 1) ? bq : bv;
    float* C          = (sel == 0) ? g_pk : (sel == 1) ? g_pq : g_pv;

    const int warp  = t >> 5;
    const int mlane = (t >> 3) & 3;
    const int nlane = t & 7;
    const int ml = warp * 32 + mlane * 8;
    const int nl = nlane * 8;

    u64 acc[8][4];
    #pragma unroll
    for (int i = 0; i < 8; i++)
        #pragma unroll
        for (int j = 0; j < 4; j++) acc[i][j] = 0ULL;

    for (int kt = 0; kt < 128; ++kt) {
        const int k0 = kt * 16;
        #pragma unroll
        for (int l = 0; l < 4; l++) {           // A tile: 128x16
            int v = t + l * 128;
            int row = v >> 2, c4 = (v & 3) * 4;
            float4 av = *(const float4*)(X + (size_t)(m0 + row) * 2048 + k0 + c4);
            As[c4 + 0][row] = av.x; As[c4 + 1][row] = av.y;
            As[c4 + 2][row] = av.z; As[c4 + 3][row] = av.w;
        }
        #pragma unroll
        for (int l = 0; l < 2; l++) {           // B tile: 64x16
            int v = t + l * 128;
            int n = v >> 2, c4 = (v & 3) * 4;
            float4 bv4 = *(const float4*)(W + (size_t)(d0 + n) * 2048 + k0 + c4);
            Bs[c4 + 0][n] = bv4.x; Bs[c4 + 1][n] = bv4.y;
            Bs[c4 + 2][n] = bv4.z; Bs[c4 + 3][n] = bv4.w;
        }
        __syncthreads();
        #pragma unroll
        for (int kk = 0; kk < 16; kk++) {
            float4 a0 = *(const float4*)&As[kk][ml];
            float4 a1 = *(const float4*)&As[kk][ml + 4];
            float4 b0 = *(const float4*)&Bs[kk][nl];
            float4 b1 = *(const float4*)&Bs[kk][nl + 4];
            u64 bb0 = pk2(b0.x, b0.y), bb1 = pk2(b0.z, b0.w);
            u64 bb2 = pk2(b1.x, b1.y), bb3 = pk2(b1.z, b1.w);
            float a[8] = {a0.x, a0.y, a0.z, a0.w, a1.x, a1.y, a1.z, a1.w};
            #pragma unroll
            for (int i = 0; i < 8; i++) {
                u64 aa = pk2(a[i], a[i]);
                acc[i][0] = fma2(aa, bb0, acc[i][0]);
                acc[i][1] = fma2(aa, bb1, acc[i][1]);
                acc[i][2] = fma2(aa, bb2, acc[i][2]);
                acc[i][3] = fma2(aa, bb3, acc[i][3]);
            }
        }
        __syncthreads();
    }
    #pragma unroll
    for (int i = 0; i < 8; i++) {
        const int m = m0 + ml + i;
        #pragma unroll
        for (int j = 0; j < 4; j++) {
            float c0, c1; upk2(acc[i][j], c0, c1);
            const int n = nl + j * 2;
            C[(size_t)m * 128 + d0 + n]     = c0 + bias[d0 + n];
            C[(size_t)m * 128 + d0 + n + 1] = c1 + bias[d0 + n + 1];
        }
    }
}

// =====================================================================
// Kernel 2: beta = sigmoid(x @ beta_w^T + beta_b). One warp per row.
// =====================================================================
__global__ void __launch_bounds__(128) beta_kernel(
    const float* __restrict__ X, const float* __restrict__ bw, const float* __restrict__ bb)
{
    const int m = blockIdx.x * 4 + (threadIdx.x >> 5);
    const int lane = threadIdx.x & 31;
    const float4* xr = (const float4*)(X + (size_t)m * 2048);
    const float4* wr = (const float4*)bw;
    float s = 0.f;
    #pragma unroll 4
    for (int i = 0; i < 16; i++) {
        float4 a = xr[i * 32 + lane];
        float4 w = wr[i * 32 + lane];
        s += a.x * w.x + a.y * w.y + a.z * w.z + a.w * w.w;
    }
    s = wsum(s);
    if (lane == 0) g_beta[m] = 1.f / (1.f + expf(-(s + bb[0])));
}

// =====================================================================
// Kernel 3: 1-D conv (k=3 over s, 128->128 ch, weights w[o][i][kh][1]) + bias + silu.
// grid (16 s-tiles, 2 o-groups of 64, 12 = arr*4+b), 256 thr, thread tile 4o x 8s.
// =====================================================================
__global__ void __launch_bounds__(256) conv_silu(
    const float* __restrict__ wk, const float* __restrict__ bk,
    const float* __restrict__ wq, const float* __restrict__ bq,
    const float* __restrict__ wv, const float* __restrict__ bv)
{
    const int arr = blockIdx.z >> 2;
    const int b   = blockIdx.z & 3;
    const float* in  = (arr == 0) ? g_pk : (arr == 1) ? g_pq : g_pv;
    float* out       = (arr == 0) ? g_ck : (arr == 1) ? g_cq : g_cv;
    const float* w   = (arr == 0) ? wk : (arr == 1) ? wq : wv;
    const float* bias= (arr == 0) ? bk : (arr == 1) ? bq : bv;

    const int s0 = blockIdx.x * 128;
    const int o0 = blockIdx.y * 64;
    __shared__ float sin_[16][130];
    __shared__ float swt[64][16][3];
    const int tid = threadIdx.x;
    const int to = tid >> 4, ts = tid & 15;
    const int o_loc = to * 4, s_loc = ts * 8;
    const float* inb = in + (size_t)b * PER_B;

    float acc[4][8];
    #pragma unroll
    for (int oo = 0; oo < 4; oo++)
        #pragma unroll
        for (int ss = 0; ss < 8; ss++) acc[oo][ss] = 0.f;

    for (int ic = 0; ic < 8; ic++) {
        for (int i = tid; i < 2080; i += 256) {
            int j = i / 130, p = i % 130;
            int gs = s0 + p - 1;
            sin_[j][p] = (gs >= 0 && gs < 2048) ? inb[(ic * 16 + j) * 2048 + gs] : 0.f;
        }
        for (int i = tid; i < 3072; i += 256) {
            int o = i / 48, rr = i % 48, j = rr / 3, kh = rr % 3;
            swt[o][j][kh] = w[((size_t)(o0 + o) * 128 + ic * 16 + j) * 9 + kh * 3 + 1];
        }
        __syncthreads();
        #pragma unroll
        for (int j = 0; j < 16; j++) {
            float xin[10];
            #pragma unroll
            for (int p = 0; p < 10; p++) xin[p] = sin_[j][s_loc + p];
            #pragma unroll
            for (int oo = 0; oo < 4; oo++) {
                float w0 = swt[o_loc + oo][j][0];
                float w1 = swt[o_loc + oo][j][1];
                float w2 = swt[o_loc + oo][j][2];
                #pragma unroll
                for (int ss = 0; ss < 8; ss++)
                    acc[oo][ss] = fmaf(w0, xin[ss],
                                   fmaf(w1, xin[ss + 1],
                                    fmaf(w2, xin[ss + 2], acc[oo][ss])));
            }
        }
        __syncthreads();
    }
    float* outb = out + (size_t)b * PER_B;
    #pragma unroll
    for (int oo = 0; oo < 4; oo++) {
        float bvv = bias[o0 + o_loc + oo];
        float* orow = outb + (size_t)(o0 + o_loc + oo) * 2048 + s0 + s_loc;
        #pragma unroll
        for (int ss = 0; ss < 8; ss++) {
            float y = acc[oo][ss] + bvv;
            orow[ss] = y / (1.f + expf(-y));
        }
    }
}

// =====================================================================
// Kernel 4: inverse L2 norms over the s axis (2048) for k and q rows.
// =====================================================================
__global__ void __launch_bounds__(128) l2norms()
{
    const int arr = blockIdx.y;                 // 0=k, 1=q
    const int idx = blockIdx.x;                 // b*128 + c, 0..511
    const float* in = ((arr == 0) ? g_ck : g_cq) + (size_t)idx * 2048;
    const int tid = threadIdx.x;
    float ss = 0.f;
    const float4* in4 = (const float4*)in;
    for (int i = tid; i < 512; i += 128) {
        float4 v = in4[i];
        ss += v.x * v.x + v.y * v.y + v.z * v.z + v.w * v.w;
    }
    ss = wsum(ss);
    __shared__ float red[4];
    if ((tid & 31) == 0) red[tid >> 5] = ss;
    __syncthreads();
    if (tid == 0) {
        float tot = red[0] + red[1] + red[2] + red[3];
        g_ninv[arr * 512 + idx] = 1.f / fmaxf(sqrtf(tot), 1e-12f);
    }
}

// =====================================================================
// Kernel 5: scale (k,q) + transpose all three to [b][t][c].
// =====================================================================
__global__ void transpose_scale()
{
    const int z = blockIdx.z;
    const int arr = z >> 2, b = z & 3;
    const float* in = (arr == 0) ? g_ck : (arr == 1) ? g_cq : g_cv;
    float* out      = (arr == 0) ? g_kT : (arr == 1) ? g_qT : g_vT;
    const int s0 = blockIdx.x * 32, c0 = blockIdx.y * 32;
    __shared__ float tile[32][33];
    const int tx = threadIdx.x, ty = threadIdx.y;
    #pragma unroll
    for (int i = 0; i < 4; i++) {
        int c = c0 + ty + i * 8;
        float sc = (arr < 2) ? g_ninv[arr * 512 + b * 128 + c] : 1.f;
        tile[ty + i * 8][tx] = in[(size_t)b * PER_B + (size_t)c * 2048 + s0 + tx] * sc;
    }
    __syncthreads();
    #pragma unroll
    for (int i = 0; i < 4; i++) {
        int s = s0 + ty + i * 8;
        out[(size_t)b * PER_B + (size_t)s * 128 + c0 + tx] = tile[tx][ty + i * 8];
    }
}

// =====================================================================
// Kernel 6: delta rule. One warp per (batch, state row r); lane holds
// S[r][lane + 32j], j=0..3. Sequential over t with 1-step prefetch.
// =====================================================================
__global__ void __launch_bounds__(128) delta_kernel()
{
    const int b  = blockIdx.x >> 5;
    const int rg = blockIdx.x & 31;
    const int warp = threadIdx.x >> 5;
    const int lane = threadIdx.x & 31;
    const int r = rg * 4 + warp;

    const float* kb = g_kT + (size_t)b * PER_B;
    const float* qb = g_qT + (size_t)b * PER_B;
    const float* vb = g_vT + (size_t)b * PER_B;
    const float* bbp = g_beta + b * 2048;
    float* ob = g_dT + (size_t)b * PER_B;

    float s0 = 0.f, s1 = 0.f, s2 = 0.f, s3 = 0.f;
    float kc0 = kb[lane], kc1 = kb[lane + 32], kc2 = kb[lane + 64], kc3 = kb[lane + 96];
    float qc0 = qb[lane], qc1 = qb[lane + 32], qc2 = qb[lane + 64], qc3 = qb[lane + 96];
    float vc = vb[r];
    float bc = bbp[0];

    for (int t = 0; t < 2048; ++t) {
        float kn0 = 0, kn1 = 0, kn2 = 0, kn3 = 0, qn0 = 0, qn1 = 0, qn2 = 0, qn3 = 0, vn = 0, bn = 0;
        if (t < 2047) {
            const float* kp = kb + (size_t)(t + 1) * 128;
            const float* qp = qb + (size_t)(t + 1) * 128;
            kn0 = kp[lane]; kn1 = kp[lane + 32]; kn2 = kp[lane + 64]; kn3 = kp[lane + 96];
            qn0 = qp[lane]; qn1 = qp[lane + 32]; qn2 = qp[lane + 64]; qn3 = qp[lane + 96];
            vn = vb[(size_t)(t + 1) * 128 + r];
            bn = bbp[t + 1];
        }
        // Sk[r]
        float pa = fmaf(kc1, s1, kc0 * s0);
        float pb = fmaf(kc3, s3, kc2 * s2);
        float p  = pa + pb;
        #pragma unroll
        for (int o = 16; o > 0; o >>= 1) p += __shfl_xor_sync(0xffffffffu, p, o);
        // update row
        float u = bc * (vc - p);
        s0 = fmaf(u, kc0, s0); s1 = fmaf(u, kc1, s1);
        s2 = fmaf(u, kc2, s2); s3 = fmaf(u, kc3, s3);
        // o[r] = S_new[r] . q
        float oa = fmaf(qc1, s1, qc0 * s0);
        float obp = fmaf(qc3, s3, qc2 * s2);
        float oo = oa + obp;
        #pragma unroll
        for (int o = 16; o > 0; o >>= 1) oo += __shfl_xor_sync(0xffffffffu, oo, o);
        if (lane == 0) ob[(size_t)t * 128 + r] = oo;

        kc0 = kn0; kc1 = kn1; kc2 = kn2; kc3 = kn3;
        qc0 = qn0; qc1 = qn1; qc2 = qn2; qc3 = qn3;
        vc = vn; bc = bn;
    }
}

// =====================================================================
// Kernel 7: RMS normalize delta over D (mean of squares, eps = FLT_EPSILON) * rms_w.
// =====================================================================
__global__ void __launch_bounds__(128) rms_kernel(const float* __restrict__ rms_w)
{
    const int m = blockIdx.x * 4 + (threadIdx.x >> 5);
    const int lane = threadIdx.x & 31;
    const float* row = g_dT + (size_t)m * 128;
    float v0 = row[lane], v1 = row[lane + 32], v2 = row[lane + 64], v3 = row[lane + 96];
    float ss = v0 * v0 + v1 * v1 + v2 * v2 + v3 * v3;
    ss = wsum(ss);
    float rs = 1.f / sqrtf(ss * (1.f / 128.f) + 1.1920928955078125e-07f);
    float* o = g_normed + (size_t)m * 128;
    o[lane]      = v0 * rs * rms_w[lane];
    o[lane + 32] = v1 * rs * rms_w[lane + 32];
    o[lane + 64] = v2 * rs * rms_w[lane + 64];
    o[lane + 96] = v3 * rs * rms_w[lane + 96];
}

// =====================================================================
// Kernel 8: output GEMM  out[8192,2048] = normed[8192,128] @ out_w^T + out_b.
// BM=128 BN=128 BK=16, 256 thr, f32x2 accumulators.
// =====================================================================
__global__ void __launch_bounds__(256) gemm_out(
    const float* __restrict__ Wo, const float* __restrict__ bo, float* __restrict__ OUT)
{
    __shared__ float As[16][128];
    __shared__ float Bs[16][128];
    const int t  = threadIdx.x;
    const int n0 = blockIdx.x * 128;
    const int m0 = blockIdx.y * 128;
    const int warp = t >> 5;
    const int wm = warp & 3, wn = warp >> 2;
    const int mlane = (t >> 3) & 3, nlane = t & 7;
    const int ml = wm * 32 + mlane * 8;
    const int nl = wn * 64 + nlane * 8;

    u64 acc[8][4];
    #pragma unroll
    for (int i = 0; i < 8; i++)
        #pragma unroll
        for (int j = 0; j < 4; j++) acc[i][j] = 0ULL;

    for (int kt = 0; kt < 8; ++kt) {
        const int k0 = kt * 16;
        #pragma unroll
        for (int l = 0; l < 2; l++) {
            int v = t + l * 256;
            int row = v >> 2, c4 = (v & 3) * 4;
            float4 av = *(const float4*)(g_normed + (size_t)(m0 + row) * 128 + k0 + c4);
            As[c4 + 0][row] = av.x; As[c4 + 1][row] = av.y;
            As[c4 + 2][row] = av.z; As[c4 + 3][row] = av.w;
        }
        #pragma unroll
        for (int l = 0; l < 2; l++) {
            int v = t + l * 256;
            int n = v >> 2, c4 = (v & 3) * 4;
            float4 bv4 = *(const float4*)(Wo + (size_t)(n0 + n) * 128 + k0 + c4);
            Bs[c4 + 0][n] = bv4.x; Bs[c4 + 1][n] = bv4.y;
            Bs[c4 + 2][n] = bv4.z; Bs[c4 + 3][n] = bv4.w;
        }
        __syncthreads();
        #pragma unroll
        for (int kk = 0; kk < 16; kk++) {
            float4 a0 = *(const float4*)&As[kk][ml];
            float4 a1 = *(const float4*)&As[kk][ml + 4];
            float4 b0 = *(const float4*)&Bs[kk][nl];
            float4 b1 = *(const float4*)&Bs[kk][nl + 4];
            u64 bb0 = pk2(b0.x, b0.y), bb1 = pk2(b0.z, b0.w);
            u64 bb2 = pk2(b1.x, b1.y), bb3 = pk2(b1.z, b1.w);
            float a[8] = {a0.x, a0.y, a0.z, a0.w, a1.x, a1.y, a1.z, a1.w};
            #pragma unroll
            for (int i = 0; i < 8; i++) {
                u64 aa = pk2(a[i], a[i]);
                acc[i][0] = fma2(aa, bb0, acc[i][0]);
                acc[i][1] = fma2(aa, bb1, acc[i][1]);
                acc[i][2] = fma2(aa, bb2, acc[i][2]);
                acc[i][3] = fma2(aa, bb3, acc[i][3]);
            }
        }
        __syncthreads();
    }
    #pragma unroll
    for (int i = 0; i < 8; i++) {
        const int m = m0 + ml + i;
        #pragma unroll
        for (int j = 0; j < 4; j++) {
            float c0, c1; upk2(acc[i][j], c0, c1);
            const int n = n0 + nl + j * 2;
            OUT[(size_t)m * 2048 + n]     = c0 + bo[n];
            OUT[(size_t)m * 2048 + n + 1] = c1 + bo[n + 1];
        }
    }
}

// =====================================================================
extern "C" void kernel_launch(void* const* d_in, const int* in_sizes, int n_in,
                              void* d_out, int out_size)
{
    const float* x    = (const float*)d_in[0];
    const float* kpw  = (const float*)d_in[1];
    const float* kpb  = (const float*)d_in[2];
    const float* qpw  = (const float*)d_in[3];
    const float* qpb  = (const float*)d_in[4];
    const float* vpw  = (const float*)d_in[5];
    const float* vpb  = (const float*)d_in[6];
    const float* kcw  = (const float*)d_in[7];
    const float* kcb  = (const float*)d_in[8];
    const float* qcw  = (const float*)d_in[9];
    const float* qcb  = (const float*)d_in[10];
    const float* vcw  = (const float*)d_in[11];
    const float* vcb  = (const float*)d_in[12];
    const float* bw   = (const float*)d_in[13];
    const float* bb   = (const float*)d_in[14];
    const float* rmsw = (const float*)d_in[15];
    const float* ow   = (const float*)d_in[16];
    const float* obias= (const float*)d_in[17];
    float* out = (float*)d_out;

    // 1) fused projections
    gemm_proj<<<dim3(6, 64), 128>>>(x, kpw, qpw, vpw, kpb, qpb, vpb);
    // 2) beta
    beta_kernel<<<2048, 128>>>(x, bw, bb);
    // 3) conv + silu for k,q,v
    conv_silu<<<dim3(16, 2, 12), 256>>>(kcw, kcb, qcw, qcb, vcw, vcb);
    // 4) L2 norms for k,q
    l2norms<<<dim3(512, 2), 128>>>();
    // 5) scale + transpose to [b][t][c]
    transpose_scale<<<dim3(64, 4, 12), dim3(32, 8)>>>();
    // 6) delta rule
    delta_kernel<<<128, 128>>>();
    // 7) RMS norm
    rms_kernel<<<2048, 128>>>(rmsw);
    // 8) output projection
    gemm_out<<<dim3(16, 64), 256>>>(ow, obias, out);
}

// round 2
// speedup vs baseline: 1.0513x; 1.0513x over previous
#include <cuda_runtime.h>
#include <math.h>

// ---------------- problem constants ----------------
#define BB 4
#define LL 2048
#define DD 128
#define MM (BB*LL)          // 8192 rows
#define PER_B (DD*LL)       // 262144 elements per batch per [D][L] buffer
#define TOT (BB*PER_B)      // 1048576

typedef unsigned long long u64;

// ---------------- scratch (static device memory; no allocation) ----------------
__device__ float g_pk[TOT];     // projection outputs [b][l][d] == conv input [b][c][s]
__device__ float g_pq[TOT];
__device__ float g_pv[TOT];
__device__ float g_ck[TOT];     // conv+silu outputs [b][c][s]
__device__ float g_cq[TOT];
__device__ float g_cv[TOT];
__device__ float g_kT[TOT];     // normalized, transposed [b][t][c]
__device__ float g_qT[TOT];
__device__ float g_vT[TOT];
__device__ float g_dT[TOT];     // delta output [b][t][c]
__device__ float g_normed[TOT]; // rms-normalized delta
__device__ float g_beta[MM];
__device__ float g_kq[MM];      // k_t . q_t per (b,t)
__device__ float g_ninv[2*512]; // inv l2 norms for k (0..511) and q (512..1023)

// ---------------- f32x2 helpers (sm_10x packed fp32 FMA) ----------------
__device__ __forceinline__ u64 pk2(float x, float y) {
    u64 r; asm("mov.b64 %0, {%1, %2};" : "=l"(r) : "f"(x), "f"(y)); return r;
}
__device__ __forceinline__ u64 fma2(u64 a, u64 b, u64 c) {
    u64 d; asm("fma.rn.f32x2 %0, %1, %2, %3;" : "=l"(d) : "l"(a), "l"(b), "l"(c)); return d;
}
__device__ __forceinline__ void upk2(u64 v, float& x, float& y) {
    asm("mov.b64 {%0, %1}, %2;" : "=f"(x), "=f"(y) : "l"(v));
}
__device__ __forceinline__ float wsum(float v) {
    #pragma unroll
    for (int o = 16; o > 0; o >>= 1) v += __shfl_xor_sync(0xffffffffu, v, o);
    return v;
}

// =====================================================================
// Kernel 1: fused k/q/v projection GEMM.
// C[8192,384] = X[8192,2048] @ Wcat^T, tiles BM=128 BN=64 BK=16, 128 thr,
// thread tile 8x8, f32x2 accumulators, reg-prefetch pipeline,
// conflict-free smem staging (thread t stages row t of the A tile).
// =====================================================================
__global__ void __launch_bounds__(128) gemm_proj(
    const float* __restrict__ X,
    const float* __restrict__ Wk, const float* __restrict__ Wq, const float* __restrict__ Wv,
    const float* __restrict__ bk, const float* __restrict__ bq, const float* __restrict__ bv)
{
    __shared__ float As[16][128];
    __shared__ float Bs[16][64];
    const int t   = threadIdx.x;
    const int nt  = blockIdx.x;           // 0..5
    const int m0  = blockIdx.y * 128;
    const int sel = nt >> 1;
    const int d0  = (nt & 1) * 64;
    const float* W    = (sel == 0) ? Wk : (sel == 1) ? Wq : Wv;
    const float* bias = (sel == 0) ? bk : (sel == 1) ? bq : bv;
    float* C          = (sel == 0) ? g_pk : (sel == 1) ? g_pq : g_pv;

    const int warp  = t >> 5;
    const int mlane = (t >> 3) & 3;
    const int nlane = t & 7;
    const int ml = warp * 32 + mlane * 8;
    const int nl = nlane * 8;

    // B loader mapping: idx = t + l*128 -> n = idx&63, c4 = (idx>>6)*4
    const int bn  = t & 63;
    const int bc0 = (t >> 6) * 4;       // l=0 chunk ; l=1 chunk = bc0+8

    u64 acc[8][4];
    #pragma unroll
    for (int i = 0; i < 8; i++)
        #pragma unroll
        for (int j = 0; j < 4; j++) acc[i][j] = 0ULL;

    float4 a_pf[4];
    float4 b_pf[2];
    const float* arow = X + (size_t)(m0 + t) * 2048;
    const float* brow = W + (size_t)(d0 + bn) * 2048;

    // prefetch kt=0
    #pragma unroll
    for (int l = 0; l < 4; l++) a_pf[l] = *(const float4*)(arow + l * 4);
    #pragma unroll
    for (int l = 0; l < 2; l++) b_pf[l] = *(const float4*)(brow + bc0 + l * 8);

    for (int kt = 0; kt < 128; ++kt) {
        // stage regs -> smem (conflict-free: lane-consecutive columns)
        #pragma unroll
        for (int l = 0; l < 4; l++) {
            As[l * 4 + 0][t] = a_pf[l].x; As[l * 4 + 1][t] = a_pf[l].y;
            As[l * 4 + 2][t] = a_pf[l].z; As[l * 4 + 3][t] = a_pf[l].w;
        }
        #pragma unroll
        for (int l = 0; l < 2; l++) {
            int c4 = bc0 + l * 8;
            Bs[c4 + 0][bn] = b_pf[l].x; Bs[c4 + 1][bn] = b_pf[l].y;
            Bs[c4 + 2][bn] = b_pf[l].z; Bs[c4 + 3][bn] = b_pf[l].w;
        }
        __syncthreads();

        // prefetch kt+1 while computing
        if (kt < 127) {
            const int k0 = (kt + 1) * 16;
            #pragma unroll
            for (int l = 0; l < 4; l++) a_pf[l] = *(const float4*)(arow + k0 + l * 4);
            #pragma unroll
            for (int l = 0; l < 2; l++) b_pf[l] = *(const float4*)(brow + k0 + bc0 + l * 8);
        }

        #pragma unroll
        for (int kk = 0; kk < 16; kk++) {
            float4 a0 = *(const float4*)&As[kk][ml];
            float4 a1 = *(const float4*)&As[kk][ml + 4];
            float4 b0 = *(const float4*)&Bs[kk][nl];
            float4 b1 = *(const float4*)&Bs[kk][nl + 4];
            u64 bb0 = pk2(b0.x, b0.y), bb1 = pk2(b0.z, b0.w);
            u64 bb2 = pk2(b1.x, b1.y), bb3 = pk2(b1.z, b1.w);
            float a[8] = {a0.x, a0.y, a0.z, a0.w, a1.x, a1.y, a1.z, a1.w};
            #pragma unroll
            for (int i = 0; i < 8; i++) {
                u64 aa = pk2(a[i], a[i]);
                acc[i][0] = fma2(aa, bb0, acc[i][0]);
                acc[i][1] = fma2(aa, bb1, acc[i][1]);
                acc[i][2] = fma2(aa, bb2, acc[i][2]);
                acc[i][3] = fma2(aa, bb3, acc[i][3]);
            }
        }
        __syncthreads();
    }
    #pragma unroll
    for (int i = 0; i < 8; i++) {
        const int m = m0 + ml + i;
        #pragma unroll
        for (int j = 0; j < 4; j++) {
            float c0, c1; upk2(acc[i][j], c0, c1);
            const int n = d0 + nl + j * 2;
            float2 o2 = make_float2(c0 + bias[n], c1 + bias[n + 1]);
            *(float2*)(C + (size_t)m * 128 + n) = o2;
        }
    }
}

// =====================================================================
// Kernel 2: beta = sigmoid(x @ beta_w^T + beta_b). One warp per row.
// =====================================================================
__global__ void __launch_bounds__(128) beta_kernel(
    const float* __restrict__ X, const float* __restrict__ bw, const float* __restrict__ bb)
{
    const int m = blockIdx.x * 4 + (threadIdx.x >> 5);
    const int lane = threadIdx.x & 31;
    const float4* xr = (const float4*)(X + (size_t)m * 2048);
    const float4* wr = (const float4*)bw;
    float s = 0.f;
    #pragma unroll 4
    for (int i = 0; i < 16; i++) {
        float4 a = xr[i * 32 + lane];
        float4 w = wr[i * 32 + lane];
        s += a.x * w.x + a.y * w.y + a.z * w.z + a.w * w.w;
    }
    s = wsum(s);
    if (lane == 0) g_beta[m] = 1.f / (1.f + expf(-(s + bb[0])));
}

// =====================================================================
// Kernel 3: 1-D conv (k=3 over s, 128->128 ch, weights w[o][i][kh][1]) + bias + silu.
// =====================================================================
__global__ void __launch_bounds__(256) conv_silu(
    const float* __restrict__ wk, const float* __restrict__ bk,
    const float* __restrict__ wq, const float* __restrict__ bq,
    const float* __restrict__ wv, const float* __restrict__ bv)
{
    const int arr = blockIdx.z >> 2;
    const int b   = blockIdx.z & 3;
    const float* in  = (arr == 0) ? g_pk : (arr == 1) ? g_pq : g_pv;
    float* out       = (arr == 0) ? g_ck : (arr == 1) ? g_cq : g_cv;
    const float* w   = (arr == 0) ? wk : (arr == 1) ? wq : wv;
    const float* bias= (arr == 0) ? bk : (arr == 1) ? bq : bv;

    const int s0 = blockIdx.x * 128;
    const int o0 = blockIdx.y * 64;
    __shared__ float sin_[16][130];
    __shared__ float swt[64][16][3];
    const int tid = threadIdx.x;
    const int to = tid >> 4, ts = tid & 15;
    const int o_loc = to * 4, s_loc = ts * 8;
    const float* inb = in + (size_t)b * PER_B;

    float acc[4][8];
    #pragma unroll
    for (int oo = 0; oo < 4; oo++)
        #pragma unroll
        for (int ss = 0; ss < 8; ss++) acc[oo][ss] = 0.f;

    for (int ic = 0; ic < 8; ic++) {
        for (int i = tid; i < 2080; i += 256) {
            int j = i / 130, p = i % 130;
            int gs = s0 + p - 1;
            sin_[j][p] = (gs >= 0 && gs < 2048) ? inb[(ic * 16 + j) * 2048 + gs] : 0.f;
        }
        for (int i = tid; i < 3072; i += 256) {
            int o = i / 48, rr = i % 48, j = rr / 3, kh = rr % 3;
            swt[o][j][kh] = w[((size_t)(o0 + o) * 128 + ic * 16 + j) * 9 + kh * 3 + 1];
        }
        __syncthreads();
        #pragma unroll
        for (int j = 0; j < 16; j++) {
            float xin[10];
            #pragma unroll
            for (int p = 0; p < 10; p++) xin[p] = sin_[j][s_loc + p];
            #pragma unroll
            for (int oo = 0; oo < 4; oo++) {
                float w0 = swt[o_loc + oo][j][0];
                float w1 = swt[o_loc + oo][j][1];
                float w2 = swt[o_loc + oo][j][2];
                #pragma unroll
                for (int ss = 0; ss < 8; ss++)
                    acc[oo][ss] = fmaf(w0, xin[ss],
                                   fmaf(w1, xin[ss + 1],
                                    fmaf(w2, xin[ss + 2], acc[oo][ss])));
            }
        }
        __syncthreads();
    }
    float* outb = out + (size_t)b * PER_B;
    #pragma unroll
    for (int oo = 0; oo < 4; oo++) {
        float bvv = bias[o0 + o_loc + oo];
        float* orow = outb + (size_t)(o0 + o_loc + oo) * 2048 + s0 + s_loc;
        #pragma unroll
        for (int ss = 0; ss < 8; ss++) {
            float y = acc[oo][ss] + bvv;
            orow[ss] = y / (1.f + expf(-y));
        }
    }
}

// =====================================================================
// Kernel 4: inverse L2 norms over the s axis (2048) for k and q rows.
// =====================================================================
__global__ void __launch_bounds__(128) l2norms()
{
    const int arr = blockIdx.y;                 // 0=k, 1=q
    const int idx = blockIdx.x;                 // b*128 + c, 0..511
    const float* in = ((arr == 0) ? g_ck : g_cq) + (size_t)idx * 2048;
    const int tid = threadIdx.x;
    float ss = 0.f;
    const float4* in4 = (const float4*)in;
    for (int i = tid; i < 512; i += 128) {
        float4 v = in4[i];
        ss += v.x * v.x + v.y * v.y + v.z * v.z + v.w * v.w;
    }
    ss = wsum(ss);
    __shared__ float red[4];
    if ((tid & 31) == 0) red[tid >> 5] = ss;
    __syncthreads();
    if (tid == 0) {
        float tot = red[0] + red[1] + red[2] + red[3];
        g_ninv[arr * 512 + idx] = 1.f / fmaxf(sqrtf(tot), 1e-12f);
    }
}

// =====================================================================
// Kernel 5: scale (k,q) + transpose all three to [b][t][c].
// =====================================================================
__global__ void transpose_scale()
{
    const int z = blockIdx.z;
    const int arr = z >> 2, b = z & 3;
    const float* in = (arr == 0) ? g_ck : (arr == 1) ? g_cq : g_cv;
    float* out      = (arr == 0) ? g_kT : (arr == 1) ? g_qT : g_vT;
    const int s0 = blockIdx.x * 32, c0 = blockIdx.y * 32;
    __shared__ float tile[32][33];
    const int tx = threadIdx.x, ty = threadIdx.y;
    #pragma unroll
    for (int i = 0; i < 4; i++) {
        int c = c0 + ty + i * 8;
        float sc = (arr < 2) ? g_ninv[arr * 512 + b * 128 + c] : 1.f;
        tile[ty + i * 8][tx] = in[(size_t)b * PER_B + (size_t)c * 2048 + s0 + tx] * sc;
    }
    __syncthreads();
    #pragma unroll
    for (int i = 0; i < 4; i++) {
        int s = s0 + ty + i * 8;
        out[(size_t)b * PER_B + (size_t)s * 128 + c0 + tx] = tile[tx][ty + i * 8];
    }
}

// =====================================================================
// Kernel 5b: kq[m] = k_t . q_t (normalized). One warp per row m = b*2048+t.
// =====================================================================
__global__ void __launch_bounds__(128) kq_kernel()
{
    const int m = blockIdx.x * 4 + (threadIdx.x >> 5);
    const int lane = threadIdx.x & 31;
    const float* kr = g_kT + (size_t)m * 128;
    const float* qr = g_qT + (size_t)m * 128;
    float s = kr[lane] * qr[lane];
    s = fmaf(kr[lane + 32], qr[lane + 32], s);
    s = fmaf(kr[lane + 64], qr[lane + 64], s);
    s = fmaf(kr[lane + 96], qr[lane + 96], s);
    s = wsum(s);
    if (lane == 0) g_kq[m] = s;
}

// =====================================================================
// Kernel 6: delta rule. One warp per (batch, state row r); lane holds
// S[r][lane + 32j]. o_r = S_old[r].q + u_r*(k.q) makes the two big
// reductions independent -> interleaved shfl trees (half the chain).
// =====================================================================
__global__ void __launch_bounds__(128) delta_kernel()
{
    const int b  = blockIdx.x >> 5;
    const int rg = blockIdx.x & 31;
    const int warp = threadIdx.x >> 5;
    const int lane = threadIdx.x & 31;
    const int r = rg * 4 + warp;

    const float* kb = g_kT + (size_t)b * PER_B;
    const float* qb = g_qT + (size_t)b * PER_B;
    const float* vb = g_vT + (size_t)b * PER_B;
    const float* bbp = g_beta + b * 2048;
    const float* kqp = g_kq + b * 2048;
    float* ob = g_dT + (size_t)b * PER_B;

    float s0 = 0.f, s1 = 0.f, s2 = 0.f, s3 = 0.f;
    float kc0 = kb[lane], kc1 = kb[lane + 32], kc2 = kb[lane + 64], kc3 = kb[lane + 96];
    float qc0 = qb[lane], qc1 = qb[lane + 32], qc2 = qb[lane + 64], qc3 = qb[lane + 96];
    float vc = vb[r];
    float bc = bbp[0];
    float kqc = kqp[0];

    for (int t = 0; t < 2048; ++t) {
        float kn0 = 0, kn1 = 0, kn2 = 0, kn3 = 0, qn0 = 0, qn1 = 0, qn2 = 0, qn3 = 0;
        float vn = 0, bn = 0, kqn = 0;
        if (t < 2047) {
            const float* kp = kb + (size_t)(t + 1) * 128;
            const float* qp = qb + (size_t)(t + 1) * 128;
            kn0 = kp[lane]; kn1 = kp[lane + 32]; kn2 = kp[lane + 64]; kn3 = kp[lane + 96];
            qn0 = qp[lane]; qn1 = qp[lane + 32]; qn2 = qp[lane + 64]; qn3 = qp[lane + 96];
            vn = vb[(size_t)(t + 1) * 128 + r];
            bn = bbp[t + 1];
            kqn = kqp[t + 1];
        }
        // two independent partial dots against S_old
        float pa = fmaf(kc1, s1, kc0 * s0);
        float pb = fmaf(kc3, s3, kc2 * s2);
        float p  = pa + pb;
        float da = fmaf(qc1, s1, qc0 * s0);
        float db = fmaf(qc3, s3, qc2 * s2);
        float d  = da + db;
        // interleaved butterfly trees (independent chains)
        #pragma unroll
        for (int o = 16; o > 0; o >>= 1) {
            p += __shfl_xor_sync(0xffffffffu, p, o);
            d += __shfl_xor_sync(0xffffffffu, d, o);
        }
        float u = bc * (vc - p);
        float oo = fmaf(u, kqc, d);
        if (lane == 0) ob[(size_t)t * 128 + r] = oo;
        // state update
        s0 = fmaf(u, kc0, s0); s1 = fmaf(u, kc1, s1);
        s2 = fmaf(u, kc2, s2); s3 = fmaf(u, kc3, s3);

        kc0 = kn0; kc1 = kn1; kc2 = kn2; kc3 = kn3;
        qc0 = qn0; qc1 = qn1; qc2 = qn2; qc3 = qn3;
        vc = vn; bc = bn; kqc = kqn;
    }
}

// =====================================================================
// Kernel 7: RMS normalize delta over D * rms_w.
// =====================================================================
__global__ void __launch_bounds__(128) rms_kernel(const float* __restrict__ rms_w)
{
    const int m = blockIdx.x * 4 + (threadIdx.x >> 5);
    const int lane = threadIdx.x & 31;
    const float* row = g_dT + (size_t)m * 128;
    float v0 = row[lane], v1 = row[lane + 32], v2 = row[lane + 64], v3 = row[lane + 96];
    float ss = v0 * v0 + v1 * v1 + v2 * v2 + v3 * v3;
    ss = wsum(ss);
    float rs = 1.f / sqrtf(ss * (1.f / 128.f) + 1.1920928955078125e-07f);
    float* o = g_normed + (size_t)m * 128;
    o[lane]      = v0 * rs * rms_w[lane];
    o[lane + 32] = v1 * rs * rms_w[lane + 32];
    o[lane + 64] = v2 * rs * rms_w[lane + 64];
    o[lane + 96] = v3 * rs * rms_w[lane + 96];
}

// =====================================================================
// Kernel 8: output GEMM  out[8192,2048] = normed[8192,128] @ out_w^T + out_b.
// BM=128 BN=128 BK=16, 256 thr, f32x2 accumulators, reg-prefetch,
// conflict-free staging.
// =====================================================================
__global__ void __launch_bounds__(256) gemm_out(
    const float* __restrict__ Wo, const float* __restrict__ bo, float* __restrict__ OUT)
{
    __shared__ float As[16][128];
    __shared__ float Bs[16][128];
    const int t  = threadIdx.x;
    const int n0 = blockIdx.x * 128;
    const int m0 = blockIdx.y * 128;
    const int warp = t >> 5;
    const int wm = warp & 3, wn = warp >> 2;
    const int mlane = (t >> 3) & 3, nlane = t & 7;
    const int ml = wm * 32 + mlane * 8;
    const int nl = wn * 64 + nlane * 8;

    const int lrow = t & 127;
    const int lc0  = (t >> 7) * 8;      // 0 or 8; chunks lc0, lc0+4

    u64 acc[8][4];
    #pragma unroll
    for (int i = 0; i < 8; i++)
        #pragma unroll
        for (int j = 0; j < 4; j++) acc[i][j] = 0ULL;

    float4 a_pf[2], b_pf[2];
    const float* arow = g_normed + (size_t)(m0 + lrow) * 128;
    const float* brow = Wo + (size_t)(n0 + lrow) * 128;

    #pragma unroll
    for (int l = 0; l < 2; l++) {
        a_pf[l] = *(const float4*)(arow + lc0 + l * 4);
        b_pf[l] = *(const float4*)(brow + lc0 + l * 4);
    }

    for (int kt = 0; kt < 8; ++kt) {
        #pragma unroll
        for (int l = 0; l < 2; l++) {
            int c4 = lc0 + l * 4;
            As[c4 + 0][lrow] = a_pf[l].x; As[c4 + 1][lrow] = a_pf[l].y;
            As[c4 + 2][lrow] = a_pf[l].z; As[c4 + 3][lrow] = a_pf[l].w;
            Bs[c4 + 0][lrow] = b_pf[l].x; Bs[c4 + 1][lrow] = b_pf[l].y;
            Bs[c4 + 2][lrow] = b_pf[l].z; Bs[c4 + 3][lrow] = b_pf[l].w;
        }
        __syncthreads();

        if (kt < 7) {
            const int k0 = (kt + 1) * 16;
            #pragma unroll
            for (int l = 0; l < 2; l++) {
                a_pf[l] = *(const float4*)(arow + k0 + lc0 + l * 4);
                b_pf[l] = *(const float4*)(brow + k0 + lc0 + l * 4);
            }
        }

        #pragma unroll
        for (int kk = 0; kk < 16; kk++) {
            float4 a0 = *(const float4*)&As[kk][ml];
            float4 a1 = *(const float4*)&As[kk][ml + 4];
            float4 b0 = *(const float4*)&Bs[kk][nl];
            float4 b1 = *(const float4*)&Bs[kk][nl + 4];
            u64 bb0 = pk2(b0.x, b0.y), bb1 = pk2(b0.z, b0.w);
            u64 bb2 = pk2(b1.x, b1.y), bb3 = pk2(b1.z, b1.w);
            float a[8] = {a0.x, a0.y, a0.z, a0.w, a1.x, a1.y, a1.z, a1.w};
            #pragma unroll
            for (int i = 0; i < 8; i++) {
                u64 aa = pk2(a[i], a[i]);
                acc[i][0] = fma2(aa, bb0, acc[i][0]);
                acc[i][1] = fma2(aa, bb1, acc[i][1]);
                acc[i][2] = fma2(aa, bb2, acc[i][2]);
                acc[i][3] = fma2(aa, bb3, acc[i][3]);
            }
        }
        __syncthreads();
    }
    #pragma unroll
    for (int i = 0; i < 8; i++) {
        const int m = m0 + ml + i;
        #pragma unroll
        for (int j = 0; j < 4; j++) {
            float c0, c1; upk2(acc[i][j], c0, c1);
            const int n = n0 + nl + j * 2;
            float2 o2 = make_float2(c0 + bo[n], c1 + bo[n + 1]);
            *(float2*)(OUT + (size_t)m * 2048 + n) = o2;
        }
    }
}

// =====================================================================
extern "C" void kernel_launch(void* const* d_in, const int* in_sizes, int n_in,
                              void* d_out, int out_size)
{
    const float* x    = (const float*)d_in[0];
    const float* kpw  = (const float*)d_in[1];
    const float* kpb  = (const float*)d_in[2];
    const float* qpw  = (const float*)d_in[3];
    const float* qpb  = (const float*)d_in[4];
    const float* vpw  = (const float*)d_in[5];
    const float* vpb  = (const float*)d_in[6];
    const float* kcw  = (const float*)d_in[7];
    const float* kcb  = (const float*)d_in[8];
    const float* qcw  = (const float*)d_in[9];
    const float* qcb  = (const float*)d_in[10];
    const float* vcw  = (const float*)d_in[11];
    const float* vcb  = (const float*)d_in[12];
    const float* bw   = (const float*)d_in[13];
    const float* bb   = (const float*)d_in[14];
    const float* rmsw = (const float*)d_in[15];
    const float* ow   = (const float*)d_in[16];
    const float* obias= (const float*)d_in[17];
    float* out = (float*)d_out;

    gemm_proj<<<dim3(6, 64), 128>>>(x, kpw, qpw, vpw, kpb, qpb, vpb);
    beta_kernel<<<2048, 128>>>(x, bw, bb);
    conv_silu<<<dim3(16, 2, 12), 256>>>(kcw, kcb, qcw, qcb, vcw, vcb);
    l2norms<<<dim3(512, 2), 128>>>();
    transpose_scale<<<dim3(64, 4, 12), dim3(32, 8)>>>();
    kq_kernel<<<2048, 128>>>();
    delta_kernel<<<128, 128>>>();
    rms_kernel<<<2048, 128>>>(rmsw);
    gemm_out<<<dim3(16, 64), 256>>>(ow, obias, out);
}